// round 17
// baseline (speedup 1.0000x reference)
#include <cuda_runtime.h>
#include <math_constants.h>

// LIF_13984413516471  — B=128, S=128, H=128, K=8.
// s += x; spike = s > th[k]; out = spike ? s : 0; s -= out — serial (i,j,k).
// Output: outs[b][i][k][j], spikes[b][i][k][j].
//
// K1 (block/batch, 128 thr): per-chunk metadata sim (spec end E, sum S,
//     EXACT silence bound M) into smem+global; then thread 0 runs the O(1)
//     chain walk: cls0 s==0 exact; cls1 silent jump; cls2 assume merge.
// K2 (block/batch, 256 thr, dyn smem): 8 warps x 16 chunks write the FULL
//     output once, each lane simming ONE trajectory from g_in[c] (cls1 ->
//     sentinel -1e30 => zeros). cls2 bad iff end != E (bitwise), flags in
//     smem. Then warp 0 repairs THIS batch in-kernel (overlapped across
//     blocks): off-chain silent -> zero-fill + O(1) jump; off-chain active
//     -> dual resim vs the g_in-trajectory (memory invariant) with
//     group-granular co-spike exit; exact bitwise chain-return.

#define BB 128
#define SS 128
#define HH 128
#define KK 8
#define NCHUNK (BB * SS)          // 16384
#define CPW 16                    // chunks per warp in K2
#define WPB 8                     // warps per block in K2 (8*16 = 128 = SS)
#define QJ 16                     // j-steps per smem tile
#define NQ (HH / QJ)              // 8
#define CH_STRIDE 130             // floats; even (STS.64) + 16-lane conflict-free
#define MARGIN 0.01f

#define BUF_FLOATS (WPB * CPW * CH_STRIDE)           // 16640
#define K2_SMEM_FLOATS (BUF_FLOATS + 5 * SS + SS/2)  // buf + 5 arrays + 2 byte arrays
#define K2_SMEM_BYTES (K2_SMEM_FLOATS * 4)

__device__ float g_E[NCHUNK];          // spec end state
__device__ float g_S[NCHUNK];          // chunk sum (per-j jumps)
__device__ float g_M[NCHUNK];          // exact linear-trajectory spike bound
__device__ float g_in[NCHUNK];         // chain state entering chunk
__device__ unsigned char g_cls[NCHUNK];

// ---------------------------------------------------------------- kernel K1
__global__ __launch_bounds__(SS) void lif_meta_state_kernel(
    const float* __restrict__ x, const float* __restrict__ th)
{
    __shared__ float smE[SS], smS[SS], smM[SS];

    const int b = blockIdx.x;
    const int i = threadIdx.x;
    const int c = b * SS + i;

    float t[KK];
#pragma unroll
    for (int k = 0; k < KK; ++k) t[k] = __ldg(th + k);

    const float4* __restrict__ xr4 =
        reinterpret_cast<const float4*>(x + (size_t)c * HH);

    float s = 0.0f;
    float p = 0.0f;                  // per-j jumped prefix
    float Mp = -CUDART_INF_F;        // exact: max_j (p_j + c(x_j))

    for (int g = 0; g < HH / 4; ++g) {
        float4 xv = xr4[g];
        float xa[4] = {xv.x, xv.y, xv.z, xv.w};
#pragma unroll
        for (int jj = 0; jj < 4; ++jj) {
            float xx = xa[jj];
            // exact per-j spike reach: cmx = max_m(m*x - th[m-1])
            float cmx = fmaf(1.0f, xx, -t[0]);
#pragma unroll
            for (int k = 1; k < KK; ++k)
                cmx = fmaxf(cmx, fmaf((float)(k + 1), xx, -t[k]));
            Mp = fmaxf(Mp, p + cmx);
            p += 8.0f * xx;
#pragma unroll
            for (int k = 0; k < KK; ++k) {
                s += xx;
                bool sp = s > t[k];
                s = sp ? 0.0f : s;
            }
        }
    }
    smE[i] = s; smS[i] = p; smM[i] = Mp;
    g_E[c] = s; g_S[c] = p; g_M[c] = Mp;
    __syncthreads();

    if (i == 0) {
        float st = 0.0f;
        for (int j = 0; j < SS; ++j) {
            int cc = b * SS + j;
            g_in[cc] = st;
            if (st == 0.0f)                     { g_cls[cc] = 0; st = smE[j]; }
            else if (st <= -(smM[j] + MARGIN))  { g_cls[cc] = 1; st += smS[j]; }
            else                                { g_cls[cc] = 2; st = smE[j]; }
        }
    }
}

// --------------------------------------------------------- shared dual resim
// Resim trajectory-b (start sb) vs trajectory-a (start sa == chunk memory).
// Diff-patch; after a co-spike both are bitwise-identical -> later writes are
// no-ops, so the merge check once per 32 substeps is exact.
__device__ __forceinline__ bool dual_patch(
    const float* __restrict__ xrow, const float* __restrict__ t,
    float sa, float sb, float* __restrict__ orow, float* __restrict__ srow,
    int write_spikes, float* end_out)
{
    const float4* __restrict__ xr4 = reinterpret_cast<const float4*>(xrow);
    float4 cur = xr4[0];
    for (int g = 0; g < HH / 4; ++g) {
        float4 nxt = (g + 1 < HH / 4) ? xr4[g + 1] : cur;
        float xa[4] = {cur.x, cur.y, cur.z, cur.w};
        bool co = false;
#pragma unroll
        for (int jj = 0; jj < 4; ++jj) {
            float xx = xa[jj];
            int j = g * 4 + jj;
#pragma unroll
            for (int k = 0; k < KK; ++k) {
                sa += xx; sb += xx;
                bool spa = sa > t[k];
                bool spb = sb > t[k];
                co = co || (spa && spb);
                int idx = k * HH + j;
                float ot = spb ? sb : 0.0f;
                float os = spa ? sa : 0.0f;
                if (ot != os) orow[idx] = ot;
                if (write_spikes && (spa != spb)) srow[idx] = spb ? 1.0f : 0.0f;
                sa = spa ? 0.0f : sa;
                sb = spb ? 0.0f : sb;
            }
        }
        if (co) return true;
        cur = nxt;
    }
    *end_out = sb;
    return false;
}

// ---------------------------------------------------------------- kernel K2
__global__ __launch_bounds__(WPB * 32) void lif_write_repair_kernel(
    const float* __restrict__ x, const float* __restrict__ th,
    float* __restrict__ outs, float* __restrict__ spikes, int write_spikes)
{
    extern __shared__ float dyn[];
    float* buf    = dyn;                       // BUF_FLOATS
    float* smIn   = dyn + BUF_FLOATS;          // SS
    float* smE    = smIn + SS;
    float* smS    = smE + SS;
    float* smM    = smS + SS;
    float* smEndv = smM + SS;
    unsigned char* smBad = (unsigned char*)(smEndv + SS);   // SS bytes
    unsigned char* smCls = smBad + SS;                      // SS bytes

    const int b    = blockIdx.x;
    const int base = b * SS;
    const int tid  = threadIdx.x;
    const int w    = tid >> 5;
    const int lane = tid & 31;

    // cooperative metadata load (batch-local)
    if (tid < SS) {
        smIn[tid]  = g_in[base + tid];
        smE[tid]   = g_E[base + tid];
        smS[tid]   = g_S[base + tid];
        smM[tid]   = g_M[base + tid];
        smBad[tid] = 0;
        smCls[tid] = g_cls[base + tid];
    }
    __syncthreads();

    float t[KK];
#pragma unroll
    for (int k = 0; k < KK; ++k) t[k] = __ldg(th + k);

    // ---------- W phase: write whole output once ----------
    const bool active = lane < CPW;
    const int cl = active ? lane : 0;
    const int li = w * CPW + cl;               // batch-local chunk 0..127
    const float* __restrict__ xr = x + (size_t)(base + li) * HH;
    float* bp = buf + li * CH_STRIDE;

    unsigned char cls = smCls[li];
    float s = (cls == 1) ? -1e30f : smIn[li];  // cls1 sentinel -> all zeros

    for (int q = 0; q < NQ; ++q) {
        if (active) {
#pragma unroll
            for (int g = 0; g < QJ / 4; ++g) {
                float4 xv = *reinterpret_cast<const float4*>(xr + q * QJ + g * 4);
                float xa[4] = {xv.x, xv.y, xv.z, xv.w};
                float o0[KK], o1[KK];
#pragma unroll
                for (int pr = 0; pr < 2; ++pr) {          // j-pairs
#pragma unroll
                    for (int jj = 0; jj < 2; ++jj) {
                        float xx = xa[pr * 2 + jj];
                        float* ob = jj ? o1 : o0;
#pragma unroll
                        for (int k = 0; k < KK; ++k) {
                            s += xx;
                            bool sp = s > t[k];
                            ob[k] = sp ? s : 0.0f;
                            s = sp ? 0.0f : s;
                        }
                    }
                    int jp = g * 4 + pr * 2;              // even, within tile
#pragma unroll
                    for (int k = 0; k < KK; ++k) {
                        float2 v2 = make_float2(o0[k], o1[k]);
                        *reinterpret_cast<float2*>(bp + k * QJ + jp) = v2;  // STS.64
                    }
                }
            }
        }
        __syncwarp();
        {
            int jf = lane & 15;
            int ch = lane >> 4;                      // 0..1
#pragma unroll
            for (int cp = 0; cp < CPW / 2; ++cp) {
                int c = cp * 2 + ch;
                int lc = w * CPW + c;
                size_t gbase = (size_t)(base + lc) * (KK * HH) + q * QJ + jf;
                const float* sbf = buf + lc * CH_STRIDE + jf;
#pragma unroll
                for (int k = 0; k < KK; ++k) {
                    float v = sbf[k * QJ];
                    outs[gbase + k * HH] = v;
                    if (write_spikes)
                        spikes[gbase + k * HH] = v > 0.0f ? 1.0f : 0.0f;
                }
            }
        }
        __syncwarp();
    }

    // chain verification: cls2 chunks must land exactly on E
    if (active && cls == 2 && s != smE[li]) { smEndv[li] = s; smBad[li] = 1; }
    __syncthreads();

    // ---------- R phase: warp 0 repairs this batch ----------
    if (w != 0) return;

    unsigned int wd = reinterpret_cast<const unsigned int*>(smBad)[lane];
    unsigned int ballot = __ballot_sync(0xFFFFFFFFu, wd != 0u);
    if (!ballot) return;

    // first bad chunk: its s_in (chain) was correct, W output valid.
    int i = 0;
    while (i < SS && !smBad[i]) ++i;
    if (i >= SS) return;
    float rs = smEndv[i];
    ++i;

    while (i < SS) {
        // exact bitwise chain-return test
        if (rs == smIn[i]) {
            while (i < SS && !smBad[i]) ++i;   // on chain until next bad
            if (i >= SS) return;
            rs = smEndv[i];         // its s_in was on-chain -> output valid
            ++i;
            continue;
        }

        // off-chain: prefetch x row two chunks ahead into L1
        if (i + 2 < SS && lane < 16)
            asm volatile("prefetch.global.L1 [%0];"
                         :: "l"(x + (size_t)(base + i + 2) * HH + lane * 8));

        int c = base + i;
        float* orow = outs + (size_t)c * (KK * HH);
        float* srow = spikes + (size_t)c * (KK * HH);

        if (rs <= -(smM[i] + MARGIN)) {
            // truly silent: outputs must be zero
            if (smCls[i] != 1) {     // memory not already zeros
                float4 z = make_float4(0.f, 0.f, 0.f, 0.f);
                float4* o4 = reinterpret_cast<float4*>(orow);
                float4* s4 = reinterpret_cast<float4*>(srow);
#pragma unroll
                for (int it = 0; it < (KK * HH / 4) / 32; ++it) {
                    o4[it * 32 + lane] = z;
                    if (write_spikes) s4[it * 32 + lane] = z;
                }
            }
            rs += smS[i];
            ++i;
            continue;
        }

        // active off-chain: memory holds the g_in-trajectory (invariant).
        float endv;
        bool merged = dual_patch(x + (size_t)c * HH, t, smIn[i], rs,
                                 orow, srow, write_spikes, &endv);
        if (merged) {
            rs = smBad[i] ? smEndv[i] : smE[i];
        } else {
            rs = endv;
        }
        ++i;
    }
}

extern "C" void kernel_launch(void* const* d_in, const int* in_sizes, int n_in,
                              void* d_out, int out_size) {
    const float* x  = (const float*)d_in[0];   // (B, S, H) f32
    const float* th = (const float*)d_in[1];   // (K,) f32
    float* outs = (float*)d_out;

    const long long N = (long long)BB * SS * KK * HH;   // 16777216
    int write_spikes = ((long long)out_size >= 2 * N) ? 1 : 0;
    float* spikes = outs + N;

    cudaFuncSetAttribute(lif_write_repair_kernel,
                         cudaFuncAttributeMaxDynamicSharedMemorySize,
                         K2_SMEM_BYTES);

    lif_meta_state_kernel<<<BB, SS>>>(x, th);
    lif_write_repair_kernel<<<BB, WPB * 32, K2_SMEM_BYTES>>>(
        x, th, outs, spikes, write_spikes);
}